// round 12
// baseline (speedup 1.0000x reference)
#include <cuda_runtime.h>
#include <cstdint>

// Sampler: temperature 0.8, top-k, top-p 0.9, inverse-CDF multinomial. f32 output.
// 3-kernel pipeline: zero counters -> parallel collect (16 blocks/row, DRAM-bound)
// -> per-row finalize (exact-k select + sort + reference-exact epilogue).

#define NT 256
#define F4PT 8
#define SEG_F4 (NT * F4PT)          // 2048 float4 = 8192 floats per segment/block
#define NBINS 4096                  // bin = flip32(bits) >> 20 (monotone in value)
#define BINSHIFT 20
#define BPT (NBINS / NT)
#define CAP 8192                    // per-row global candidate capacity
#define MAXB 256                    // max batch rows supported
#define EPI_N 512
#define MAXEPI 256

typedef unsigned long long u64;
typedef unsigned int u32;

__device__ u64 g_cand[MAXB * CAP];  // 16 MB static scratch (allowed: no alloc)
__device__ int g_cnt[MAXB];

__device__ __forceinline__ u32 flip32(u32 f) {
    return (f & 0x80000000u) ? ~f : (f | 0x80000000u);
}
__device__ __forceinline__ u32 unflip32(u32 g) {
    return (g & 0x80000000u) ? (g & 0x7FFFFFFFu) : ~g;
}

__device__ __forceinline__ int read_k(const int* kptr) {
    int k = 50;
    if (kptr) {
        int kv = kptr[0];
        if (kv >= 1 && kv <= 100000) k = kv;
        else {
            float kf = __int_as_float(kv);
            if (kf >= 1.0f && kf <= 100000.0f) k = (int)kf;
        }
    }
    return max(1, min(k, MAXEPI));
}

// Minimal bin with suffix count >= target; thr = bin<<BINSHIFT (0 if total<target).
__device__ void select_threshold(const u32* __restrict__ hist, int target,
                                 u32* res_thr, u32* partial) {
    const int tid = threadIdx.x;
    u32 s = 0;
    const int hi = NBINS - BPT * tid;
#pragma unroll
    for (int i = 0; i < BPT; i++) s += hist[hi - 1 - i];
    partial[tid] = s;
    __syncthreads();
    if (tid < 32) {
        u32 s8 = 0;
#pragma unroll
        for (int j = 0; j < 8; j++) s8 += partial[tid * 8 + j];
        u32 c = s8;
#pragma unroll
        for (int d = 1; d < 32; d <<= 1) {
            u32 nb = __shfl_up_sync(0xffffffffu, c, d);
            if (tid >= d) c += nb;
        }
        unsigned ball = __ballot_sync(0xffffffffu, c >= (u32)target);
        if (ball == 0) {
            if (tid == 31) *res_thr = 0u;
        } else {
            int L = __ffs(ball) - 1;
            if (tid == L) {
                u32 cc = c - s8;
                u32 thr = 0u;
                bool done = false;
                for (int t2 = 8 * L; t2 < 8 * L + 8 && !done; t2++) {
                    const int h2 = NBINS - BPT * t2;
                    for (int b = h2 - 1; b >= h2 - BPT; b--) {
                        cc += hist[b];
                        if (cc >= (u32)target) { thr = ((u32)b) << BINSHIFT; done = true; break; }
                    }
                }
                *res_thr = thr;
            }
        }
    }
    __syncthreads();
}

// Warp-aggregated append into a GLOBAL per-row buffer (one global atomic per warp).
__device__ __forceinline__ void warp_append_g(u64* cand, int* cnt, bool p, u64 key) {
    unsigned m = __ballot_sync(0xffffffffu, p);
    if (m == 0) return;
    int leader = __ffs(m) - 1;
    int lane = threadIdx.x & 31;
    int base = 0;
    if (lane == leader) base = atomicAdd(cnt, __popc(m));
    base = __shfl_sync(0xffffffffu, base, leader);
    if (p) {
        int off = base + __popc(m & ((1u << lane) - 1u));
        if (off < CAP) cand[off] = key;
    }
}

// ---------------- kernel 0: reset counters ----------------
__global__ void k_zero() {
    int i = threadIdx.x + blockIdx.x * blockDim.x;
    if (i < MAXB) g_cnt[i] = 0;
}

// ---------------- kernel 1: collect (grid = nseg x B) ----------------
__global__ __launch_bounds__(NT)
void k_collect(const float* __restrict__ logits,
               const int* __restrict__ kptr, int V)
{
    __shared__ u32 hist[NBINS];
    __shared__ u32 partial[NT];
    __shared__ u32 s_thr;

    const int seg = blockIdx.x;
    const int row = blockIdx.y;
    const int tid = threadIdx.x;
    const int nf4 = V >> 2;
    const int nseg = gridDim.x;
    const float NEG = __int_as_float(0xff800000);
    const int k = read_k(kptr);

    const float4* __restrict__ rp =
        reinterpret_cast<const float4*>(logits + (size_t)row * (size_t)V);

    for (int i = tid; i < NBINS; i += NT) hist[i] = 0u;

    // front-batched segment load (8 x LDG.128 per thread)
    const int base = seg * SEG_F4;
    float4 v[F4PT];
#pragma unroll
    for (int q = 0; q < F4PT; q++) {
        int f4i = base + q * NT + tid;
        v[q] = (f4i < nf4) ? rp[f4i] : make_float4(NEG, NEG, NEG, NEG);
    }
    __syncthreads();   // hist zeroed

    // full-segment histogram
#pragma unroll
    for (int q = 0; q < F4PT; q++) {
        int f4i = base + q * NT + tid;
        if (f4i < nf4) {
            const float vv[4] = {v[q].x, v[q].y, v[q].z, v[q].w};
#pragma unroll
            for (int e = 0; e < 4; e++)
                atomicAdd(&hist[flip32(__float_as_uint(vv[e])) >> BINSHIFT], 1u);
        }
    }
    __syncthreads();

    // local threshold: segment-kth bin floor <= any global top-k element in this
    // segment (global kth >= segment kth) -> never excludes a true candidate.
    select_threshold(hist, k, &s_thr, partial);
    const u32 thr = s_thr;

    u64* cand = g_cand + (size_t)row * CAP;
#pragma unroll
    for (int q = 0; q < F4PT; q++) {
        int f4i = base + q * NT + tid;
        const float vv[4] = {v[q].x, v[q].y, v[q].z, v[q].w};
#pragma unroll
        for (int e = 0; e < 4; e++) {
            u32 fb = flip32(__float_as_uint(vv[e]));
            bool p = (f4i < nf4) && (fb >= thr);
            u64 key = ((u64)fb << 32) | (u32)(0xFFFFFFFFu - (u32)(f4i * 4 + e));
            warp_append_g(cand, &g_cnt[row], p, key);
        }
    }

    // scalar tail (V % 4 != 0), last segment, warp 0 (warp-collective append)
    if (seg == nseg - 1 && tid < 32) {
        int idx = nf4 * 4 + tid;
        bool inb = idx < V;
        float val = inb ? logits[(size_t)row * (size_t)V + idx] : NEG;
        u32 fb = flip32(__float_as_uint(val));
        u64 key = ((u64)fb << 32) | (u32)(0xFFFFFFFFu - (u32)idx);
        warp_append_g(cand, &g_cnt[row], inb && (fb >= thr), key);
    }
}

// ---------------- kernel 2: finalize (grid = B) ----------------
__global__ __launch_bounds__(NT)
void k_finalize(const float* __restrict__ u,
                const int* __restrict__ kptr,
                float* __restrict__ out, int V)
{
    __shared__ u32 hist[NBINS];
    __shared__ u64 ep[EPI_N];
    __shared__ u32 partial[NT];
    __shared__ u32 s_thr;
    __shared__ int s_cnt2;
    __shared__ float sx[MAXEPI];
    __shared__ float se[MAXEPI];
    __shared__ int   sid[MAXEPI];

    const int row = blockIdx.x;
    const int tid = threadIdx.x;
    const int k = read_k(kptr);
    const u64* cand = g_cand + (size_t)row * CAP;
    const int cnt = min(g_cnt[row], CAP);

    for (int i = tid; i < NBINS; i += NT) hist[i] = 0u;
    if (tid == 0) s_cnt2 = 0;
    __syncthreads();

    for (int i = tid; i < cnt; i += NT)
        atomicAdd(&hist[(u32)(cand[i] >> 32) >> BINSHIFT], 1u);
    __syncthreads();

    select_threshold(hist, k, &s_thr, partial);
    const u32 thr2 = s_thr;

    for (int i = tid; i < cnt; i += NT) {
        u64 key = cand[i];
        if ((u32)(key >> 32) >= thr2) {
            int p = atomicAdd(&s_cnt2, 1);
            if (p < EPI_N) ep[p] = key;
        }
    }
    __syncthreads();
    const int c2 = min(s_cnt2, EPI_N);

    // bitonic sort desc (value desc, index asc on ties)
    int n = 1;
    while (n < c2) n <<= 1;
    for (int j = c2 + tid; j < n; j += NT) ep[j] = 0ull;
    __syncthreads();
    for (int k2 = 2; k2 <= n; k2 <<= 1) {
        for (int s = k2 >> 1; s > 0; s >>= 1) {
            for (int j = tid; j < n; j += NT) {
                int l = j ^ s;
                if (l > j) {
                    u64 a = ep[j], b = ep[l];
                    bool desc = ((j & k2) == 0);
                    if ((a < b) == desc) { ep[j] = b; ep[l] = a; }
                }
            }
            __syncthreads();
        }
    }

    const int L = min(c2, MAXEPI);
    for (int i = tid; i < L; i += NT) {
        u64 key = ep[i];
        sx[i]  = __fdiv_rn(__uint_as_float(unflip32((u32)(key >> 32))), 0.8f);
        sid[i] = (int)(0xFFFFFFFFu - (u32)(key & 0xFFFFFFFFu));
    }
    __syncthreads();

    // serial epilogue — bit-identical to the passing R11 kernel
    if (tid == 0) {
        int ans = V;
        if (L >= 1) {
            int kc = min(k, L);
            const float x0 = sx[0];
            const float kth = sx[kc - 1];
            int kk = kc;
            while (kk < L && sx[kk] >= kth) kk++;

            float d1 = 0.f;
            for (int i = 0; i < kk; i++) {
                float ee = expf(__fadd_rn(sx[i], -x0));
                se[i] = ee;
                d1 = __fadd_rn(d1, ee);
            }
            float cprev = 0.f;
            int m = 0;
            for (int i = 0; i < kk; i++) {
                if (i > 0 && cprev > 0.9f) break;
                m++;
                cprev = __fadd_rn(cprev, __fdiv_rn(se[i], d1));
            }
            for (int i = 1; i < m; i++) {
                int idv = sid[i]; float ev = se[i]; int j = i - 1;
                while (j >= 0 && sid[j] > idv) {
                    sid[j + 1] = sid[j]; se[j + 1] = se[j]; j--;
                }
                sid[j + 1] = idv; se[j + 1] = ev;
            }
            float d2 = 0.f;
            for (int i = 0; i < m; i++) d2 = __fadd_rn(d2, se[i]);

            const float uu = u ? u[row] : 0.5f;
            float S = 0.f;
            for (int i = 0; i < m; i++) {
                S = __fadd_rn(S, __fdiv_rn(se[i], d2));
                if (S > uu) { ans = sid[i]; break; }
            }
        }
        out[row] = (float)ans;   // float32 output (ids < 2^24 exact)
    }
}

extern "C" void kernel_launch(void* const* d_in, const int* in_sizes, int n_in,
                              void* d_out, int out_size) {
    int li = 0;
    for (int i = 1; i < n_in; i++)
        if (in_sizes[i] > in_sizes[li]) li = i;

    const int B = out_size;
    const float* logits = (const float*)d_in[li];
    const float* u = nullptr;
    const int* kp = nullptr;
    for (int i = 0; i < n_in; i++) {
        if (i == li) continue;
        if (in_sizes[i] == B) u = (const float*)d_in[i];
        else if (in_sizes[i] == 1) kp = (const int*)d_in[i];
    }
    if (!u) {
        for (int i = 0; i < n_in; i++)
            if (i != li && in_sizes[i] != 1) { u = (const float*)d_in[i]; break; }
    }

    int V = in_sizes[li] / B;
    if (V * B != in_sizes[li]) {
        int Vb = in_sizes[li] / 4 / B;
        if (Vb * B * 4 == in_sizes[li]) V = Vb;
    }

    const int nf4 = V >> 2;
    const int nseg = (nf4 + SEG_F4 - 1) / SEG_F4;

    k_zero<<<1, 256>>>();
    k_collect<<<dim3(nseg, B), NT>>>(logits, kp, V);
    k_finalize<<<B, NT>>>(u, kp, (float*)d_out, V);
}

// round 13
// speedup vs baseline: 1.0234x; 1.0234x over previous
#include <cuda_runtime.h>
#include <cstdint>

// Sampler: temperature 0.8, top-k, top-p 0.9, inverse-CDF multinomial. f32 output.
// 3-kernel pipeline:
//   k_thresh  (grid=B)      : per-row threshold from first 8192 elems + counter reset
//   k_collect (grid=16 x B) : filter-only stream, fmax-tree predicate (no histogram!)
//   k_finalize(grid=B)      : exact-k select + sort + reference-exact epilogue

#define NT 256
#define F4PT 8
#define SEG_F4 (NT * F4PT)          // 2048 float4 = 8192 floats per segment/block
#define NBINS 4096                  // bin = flip32(bits) >> 20 (monotone in value)
#define BINSHIFT 20
#define BPT (NBINS / NT)
#define CAP 8192                    // per-row global candidate capacity
#define MAXB 256
#define EPI_N 512
#define MAXEPI 256

typedef unsigned long long u64;
typedef unsigned int u32;

__device__ u64   g_cand[MAXB * CAP];   // static scratch (no allocation)
__device__ int   g_cnt[MAXB];
__device__ float g_thr[MAXB];          // threshold as float (flip map is monotone)

__device__ __forceinline__ u32 flip32(u32 f) {
    return (f & 0x80000000u) ? ~f : (f | 0x80000000u);
}
__device__ __forceinline__ u32 unflip32(u32 g) {
    return (g & 0x80000000u) ? (g & 0x7FFFFFFFu) : ~g;
}

__device__ __forceinline__ int read_k(const int* kptr) {
    int k = 50;
    if (kptr) {
        int kv = kptr[0];
        if (kv >= 1 && kv <= 100000) k = kv;
        else {
            float kf = __int_as_float(kv);
            if (kf >= 1.0f && kf <= 100000.0f) k = (int)kf;
        }
    }
    return max(1, min(k, MAXEPI));
}

// Minimal bin with suffix count >= target; thr = bin<<BINSHIFT (0 if total<target).
__device__ void select_threshold(const u32* __restrict__ hist, int target,
                                 u32* res_thr, u32* partial) {
    const int tid = threadIdx.x;
    u32 s = 0;
    const int hi = NBINS - BPT * tid;
#pragma unroll
    for (int i = 0; i < BPT; i++) s += hist[hi - 1 - i];
    partial[tid] = s;
    __syncthreads();
    if (tid < 32) {
        u32 s8 = 0;
#pragma unroll
        for (int j = 0; j < 8; j++) s8 += partial[tid * 8 + j];
        u32 c = s8;
#pragma unroll
        for (int d = 1; d < 32; d <<= 1) {
            u32 nb = __shfl_up_sync(0xffffffffu, c, d);
            if (tid >= d) c += nb;
        }
        unsigned ball = __ballot_sync(0xffffffffu, c >= (u32)target);
        if (ball == 0) {
            if (tid == 31) *res_thr = 0u;
        } else {
            int L = __ffs(ball) - 1;
            if (tid == L) {
                u32 cc = c - s8;
                u32 thr = 0u;
                bool done = false;
                for (int t2 = 8 * L; t2 < 8 * L + 8 && !done; t2++) {
                    const int h2 = NBINS - BPT * t2;
                    for (int b = h2 - 1; b >= h2 - BPT; b--) {
                        cc += hist[b];
                        if (cc >= (u32)target) { thr = ((u32)b) << BINSHIFT; done = true; break; }
                    }
                }
                *res_thr = thr;
            }
        }
    }
    __syncthreads();
}

// Warp-aggregated append into a global per-row buffer (one global atomic per warp).
__device__ __forceinline__ void warp_append_g(u64* cand, int* cnt, bool p, u64 key) {
    unsigned m = __ballot_sync(0xffffffffu, p);
    if (m == 0) return;
    int leader = __ffs(m) - 1;
    int lane = threadIdx.x & 31;
    int base = 0;
    if (lane == leader) base = atomicAdd(cnt, __popc(m));
    base = __shfl_sync(0xffffffffu, base, leader);
    if (p) {
        int off = base + __popc(m & ((1u << lane) - 1u));
        if (off < CAP) cand[off] = key;
    }
}

// ---------------- kernel 1: per-row threshold (first 8192 elements) ----------------
__global__ __launch_bounds__(NT)
void k_thresh(const float* __restrict__ logits,
              const int* __restrict__ kptr, int V)
{
    __shared__ u32 hist[NBINS];
    __shared__ u32 partial[NT];
    __shared__ u32 s_thr;

    const int row = blockIdx.x;
    const int tid = threadIdx.x;
    const int nf4 = V >> 2;
    const float NEG = __int_as_float(0xff800000);
    const int k = read_k(kptr);

    const float4* __restrict__ rp =
        reinterpret_cast<const float4*>(logits + (size_t)row * (size_t)V);

    for (int i = tid; i < NBINS; i += NT) hist[i] = 0u;

    float4 v[F4PT];
#pragma unroll
    for (int q = 0; q < F4PT; q++) {
        int f4i = q * NT + tid;
        v[q] = (f4i < nf4) ? rp[f4i] : make_float4(NEG, NEG, NEG, NEG);
    }
    __syncthreads();

#pragma unroll
    for (int q = 0; q < F4PT; q++) {
        int f4i = q * NT + tid;
        if (f4i < nf4) {
            const float vv[4] = {v[q].x, v[q].y, v[q].z, v[q].w};
#pragma unroll
            for (int e = 0; e < 4; e++)
                atomicAdd(&hist[flip32(__float_as_uint(vv[e])) >> BINSHIFT], 1u);
        }
    }
    __syncthreads();

    // chunk0-kth bin floor <= row-kth: never excludes a true top-k element
    select_threshold(hist, k, &s_thr, partial);

    if (tid == 0) {
        u32 thr = s_thr;
        // flip is monotone: fb >= thr  <=>  v >= unflip(thr). Guard thr==0 -> -inf.
        g_thr[row] = (thr == 0u) ? NEG : __uint_as_float(unflip32(thr));
        g_cnt[row] = 0;
    }
}

// ---------------- kernel 2: collect (grid = nseg x B, filter only) ----------------
__global__ __launch_bounds__(NT)
void k_collect(const float* __restrict__ logits, int V)
{
    const int seg = blockIdx.x;
    const int row = blockIdx.y;
    const int tid = threadIdx.x;
    const int nf4 = V >> 2;
    const int nseg = gridDim.x;
    const float NEG = __int_as_float(0xff800000);

    const float t = g_thr[row];
    u64* cand = g_cand + (size_t)row * CAP;

    const float4* __restrict__ rp =
        reinterpret_cast<const float4*>(logits + (size_t)row * (size_t)V);

    // front-batched segment load (8 x LDG.128 per thread, MLP=8)
    const int base = seg * SEG_F4;
    float4 v[F4PT];
#pragma unroll
    for (int q = 0; q < F4PT; q++) {
        int f4i = base + q * NT + tid;
        v[q] = (f4i < nf4) ? rp[f4i] : make_float4(NEG, NEG, NEG, NEG);
    }

    // filter: fmax tree per float4 + one ballot; detail path is warp-uniform & rare
#pragma unroll
    for (int q = 0; q < F4PT; q++) {
        const float4 a = v[q];
        const float gm = fmaxf(fmaxf(a.x, a.y), fmaxf(a.z, a.w));
        if (__ballot_sync(0xffffffffu, gm >= t)) {
            const int f4i = base + q * NT + tid;
            const float vv[4] = {a.x, a.y, a.z, a.w};
#pragma unroll
            for (int e = 0; e < 4; e++) {
                bool p = vv[e] >= t;   // OOB lanes hold -inf -> false
                u64 key = ((u64)flip32(__float_as_uint(vv[e])) << 32)
                        | (u32)(0xFFFFFFFFu - (u32)(f4i * 4 + e));
                warp_append_g(cand, &g_cnt[row], p, key);
            }
        }
    }

    // scalar tail (V % 4 != 0), last segment, warp 0 (warp-collective append)
    if (seg == nseg - 1 && tid < 32) {
        int idx = nf4 * 4 + tid;
        bool inb = idx < V;
        float val = inb ? logits[(size_t)row * (size_t)V + idx] : NEG;
        u64 key = ((u64)flip32(__float_as_uint(val)) << 32)
                | (u32)(0xFFFFFFFFu - (u32)idx);
        warp_append_g(cand, &g_cnt[row], inb && (val >= t), key);
    }
}

// ---------------- kernel 3: finalize (grid = B) ----------------
__global__ __launch_bounds__(NT)
void k_finalize(const float* __restrict__ u,
                const int* __restrict__ kptr,
                float* __restrict__ out, int V)
{
    __shared__ u32 hist[NBINS];
    __shared__ u64 ep[EPI_N];
    __shared__ u32 partial[NT];
    __shared__ u32 s_thr;
    __shared__ int s_cnt2;
    __shared__ float sx[MAXEPI];
    __shared__ float se[MAXEPI];
    __shared__ int   sid[MAXEPI];

    const int row = blockIdx.x;
    const int tid = threadIdx.x;
    const int k = read_k(kptr);
    const u64* cand = g_cand + (size_t)row * CAP;
    const int cnt = min(g_cnt[row], CAP);

    for (int i = tid; i < NBINS; i += NT) hist[i] = 0u;
    if (tid == 0) s_cnt2 = 0;
    __syncthreads();

    for (int i = tid; i < cnt; i += NT)
        atomicAdd(&hist[(u32)(cand[i] >> 32) >> BINSHIFT], 1u);
    __syncthreads();

    select_threshold(hist, k, &s_thr, partial);
    const u32 thr2 = s_thr;

    for (int i = tid; i < cnt; i += NT) {
        u64 key = cand[i];
        if ((u32)(key >> 32) >= thr2) {
            int p = atomicAdd(&s_cnt2, 1);
            if (p < EPI_N) ep[p] = key;
        }
    }
    __syncthreads();
    const int c2 = min(s_cnt2, EPI_N);

    // bitonic sort desc (value desc, index asc on ties)
    int n = 1;
    while (n < c2) n <<= 1;
    for (int j = c2 + tid; j < n; j += NT) ep[j] = 0ull;
    __syncthreads();
    for (int k2 = 2; k2 <= n; k2 <<= 1) {
        for (int s = k2 >> 1; s > 0; s >>= 1) {
            for (int j = tid; j < n; j += NT) {
                int l = j ^ s;
                if (l > j) {
                    u64 a = ep[j], b = ep[l];
                    bool desc = ((j & k2) == 0);
                    if ((a < b) == desc) { ep[j] = b; ep[l] = a; }
                }
            }
            __syncthreads();
        }
    }

    const int L = min(c2, MAXEPI);
    for (int i = tid; i < L; i += NT) {
        u64 key = ep[i];
        sx[i]  = __fdiv_rn(__uint_as_float(unflip32((u32)(key >> 32))), 0.8f);
        sid[i] = (int)(0xFFFFFFFFu - (u32)(key & 0xFFFFFFFFu));
    }
    __syncthreads();

    // serial epilogue — bit-identical to the passing R11/R12 kernel
    if (tid == 0) {
        int ans = V;
        if (L >= 1) {
            int kc = min(k, L);
            const float x0 = sx[0];
            const float kth = sx[kc - 1];
            int kk = kc;
            while (kk < L && sx[kk] >= kth) kk++;

            float d1 = 0.f;
            for (int i = 0; i < kk; i++) {
                float ee = expf(__fadd_rn(sx[i], -x0));
                se[i] = ee;
                d1 = __fadd_rn(d1, ee);
            }
            float cprev = 0.f;
            int m = 0;
            for (int i = 0; i < kk; i++) {
                if (i > 0 && cprev > 0.9f) break;
                m++;
                cprev = __fadd_rn(cprev, __fdiv_rn(se[i], d1));
            }
            for (int i = 1; i < m; i++) {
                int idv = sid[i]; float ev = se[i]; int j = i - 1;
                while (j >= 0 && sid[j] > idv) {
                    sid[j + 1] = sid[j]; se[j + 1] = se[j]; j--;
                }
                sid[j + 1] = idv; se[j + 1] = ev;
            }
            float d2 = 0.f;
            for (int i = 0; i < m; i++) d2 = __fadd_rn(d2, se[i]);

            const float uu = u ? u[row] : 0.5f;
            float S = 0.f;
            for (int i = 0; i < m; i++) {
                S = __fadd_rn(S, __fdiv_rn(se[i], d2));
                if (S > uu) { ans = sid[i]; break; }
            }
        }
        out[row] = (float)ans;   // float32 output (ids < 2^24 exact)
    }
}

extern "C" void kernel_launch(void* const* d_in, const int* in_sizes, int n_in,
                              void* d_out, int out_size) {
    int li = 0;
    for (int i = 1; i < n_in; i++)
        if (in_sizes[i] > in_sizes[li]) li = i;

    const int B = out_size;
    const float* logits = (const float*)d_in[li];
    const float* u = nullptr;
    const int* kp = nullptr;
    for (int i = 0; i < n_in; i++) {
        if (i == li) continue;
        if (in_sizes[i] == B) u = (const float*)d_in[i];
        else if (in_sizes[i] == 1) kp = (const int*)d_in[i];
    }
    if (!u) {
        for (int i = 0; i < n_in; i++)
            if (i != li && in_sizes[i] != 1) { u = (const float*)d_in[i]; break; }
    }

    int V = in_sizes[li] / B;
    if (V * B != in_sizes[li]) {
        int Vb = in_sizes[li] / 4 / B;
        if (Vb * B * 4 == in_sizes[li]) V = Vb;
    }

    const int nf4 = V >> 2;
    const int nseg = (nf4 + SEG_F4 - 1) / SEG_F4;

    k_thresh<<<B, NT>>>(logits, kp, V);
    k_collect<<<dim3(nseg, B), NT>>>(logits, V);
    k_finalize<<<B, NT>>>(u, kp, (float*)d_out, V);
}

// round 14
// speedup vs baseline: 2.6290x; 2.5689x over previous
#include <cuda_runtime.h>
#include <cstdint>

// Sampler: temperature 0.8, top-k, top-p 0.9, inverse-CDF multinomial. f32 output.
// SINGLE kernel (R11 structure, measured baseline 82.8us) with its two profiled
// deficiencies fixed: 4x occupancy (NT=1024) and a per-thread fmax-tree prefilter
// replacing the per-element warp-collective append.

#define NT 1024
#define F4PT 8
#define CHUNK_F4 (NT * F4PT)        // 8192 float4 = 32768 floats / chunk
#define NBINS 4096                  // bin = flip32(bits) >> 20 (monotone in value)
#define BINSHIFT 20
#define BPT (NBINS / NT)            // 4 bins per thread
#define BUF_N 2560
#define EPI_N 512
#define MAXEPI 256

typedef unsigned long long u64;
typedef unsigned int u32;

__device__ __forceinline__ u32 flip32(u32 f) {
    return (f & 0x80000000u) ? ~f : (f | 0x80000000u);
}
__device__ __forceinline__ u32 unflip32(u32 g) {
    return (g & 0x80000000u) ? (g & 0x7FFFFFFFu) : ~g;
}

struct Sh {
    int cnt;
    int cnt2;
    u32 thr1, thr2;
    float tf;            // threshold as float (flip map is monotone)
    float x[MAXEPI];
    float e[MAXEPI];
    int   id[MAXEPI];
};

// Minimal bin with suffix count >= target; thr = bin<<BINSHIFT (0 if total<target).
// NT=1024: thread t covers BPT=4 bins; 32 leader lanes each own 32 partials.
__device__ void select_threshold(const u32* __restrict__ hist, int target,
                                 u32* res_thr, u32* partial) {
    const int tid = threadIdx.x;
    u32 s = 0;
    const int hi = NBINS - BPT * tid;   // t=0 covers top bins
#pragma unroll
    for (int i = 0; i < BPT; i++) s += hist[hi - 1 - i];
    partial[tid] = s;
    __syncthreads();
    if (tid < 32) {
        u32 s8 = 0;
#pragma unroll
        for (int j = 0; j < 32; j++) s8 += partial[tid * 32 + j];
        u32 c = s8;                      // inclusive scan, lanes = descending bins
#pragma unroll
        for (int d = 1; d < 32; d <<= 1) {
            u32 nb = __shfl_up_sync(0xffffffffu, c, d);
            if (tid >= d) c += nb;
        }
        unsigned ball = __ballot_sync(0xffffffffu, c >= (u32)target);
        if (ball == 0) {
            if (tid == 31) *res_thr = 0u;
        } else {
            int L = __ffs(ball) - 1;
            if (tid == L) {
                u32 cc = c - s8;
                u32 thr = 0u;
                bool done = false;
                for (int t2 = 32 * L; t2 < 32 * L + 32 && !done; t2++) {
                    const int h2 = NBINS - BPT * t2;
                    for (int b = h2 - 1; b >= h2 - BPT; b--) {
                        cc += hist[b];
                        if (cc >= (u32)target) { thr = ((u32)b) << BINSHIFT; done = true; break; }
                    }
                }
                *res_thr = thr;
            }
        }
    }
    __syncthreads();
}

__global__ __launch_bounds__(NT)
void Sampler_24446953849417_kernel(const float* __restrict__ logits,
                                   const float* __restrict__ u,
                                   const int* __restrict__ kptr,
                                   float* __restrict__ out, int V)
{
    __shared__ u32 hist[NBINS];        // 16 KB
    __shared__ u64 buf[BUF_N];         // 20 KB
    __shared__ u64 ep[EPI_N];          // 4 KB
    __shared__ u32 partial[NT];        // 4 KB
    __shared__ Sh sh;                  // ~3 KB   (total ~47.2 KB < 48 KB)

    const int row = blockIdx.x;
    const int tid = threadIdx.x;

    const float4* __restrict__ rp =
        reinterpret_cast<const float4*>(logits + (size_t)row * (size_t)V);
    const int nf4 = V >> 2;
    const int nchunks = (nf4 + CHUNK_F4 - 1) / CHUNK_F4;
    const float NEG = __int_as_float(0xff800000);

    int k = 50;
    if (kptr) {
        int kv = kptr[0];
        if (kv >= 1 && kv <= 100000) k = kv;
        else {
            float kf = __int_as_float(kv);
            if (kf >= 1.0f && kf <= 100000.0f) k = (int)kf;
        }
    }
    k = max(1, min(k, MAXEPI));

    for (int i = tid; i < NBINS; i += NT) hist[i] = 0u;
    if (tid == 0) { sh.cnt = 0; sh.cnt2 = 0; }

    // ---- chunk 0 (32768 elems) into registers ----
    float4 v0[F4PT];
#pragma unroll
    for (int q = 0; q < F4PT; q++) {
        int f4i = q * NT + tid;
        v0[q] = (f4i < nf4) ? rp[f4i] : make_float4(NEG, NEG, NEG, NEG);
    }
    __syncthreads();

    // ---- chunk-0 histogram (primes threshold; ~32 spread shared atomics/thread) ----
#pragma unroll
    for (int q = 0; q < F4PT; q++) {
        int f4i = q * NT + tid;
        if (f4i < nf4) {
            const float vv[4] = {v0[q].x, v0[q].y, v0[q].z, v0[q].w};
#pragma unroll
            for (int e = 0; e < 4; e++)
                atomicAdd(&hist[flip32(__float_as_uint(vv[e])) >> BINSHIFT], 1u);
        }
    }
    __syncthreads();

    // thr1 <= chunk0-kth <= row-kth : never excludes a true top-k element
    select_threshold(hist, k, &sh.thr1, partial);
    if (tid == 0) sh.tf = (sh.thr1 == 0u) ? NEG : __uint_as_float(unflip32(sh.thr1));
    __syncthreads();
    const float tf = sh.tf;

    // ---- chunk-0 candidates (per-thread fmax prefilter, rare detail path) ----
#pragma unroll
    for (int q = 0; q < F4PT; q++) {
        const float4 a = v0[q];
        const float gm = fmaxf(fmaxf(a.x, a.y), fmaxf(a.z, a.w));
        if (gm >= tf) {
            const int f4i = q * NT + tid;
            const float vv[4] = {a.x, a.y, a.z, a.w};
#pragma unroll
            for (int e = 0; e < 4; e++) {
                if (vv[e] >= tf) {   // OOB lanes hold -inf -> false
                    int s = atomicAdd(&sh.cnt, 1);
                    if (s < BUF_N)
                        buf[s] = ((u64)flip32(__float_as_uint(vv[e])) << 32)
                               | (u32)(0xFFFFFFFFu - (u32)(f4i * 4 + e));
                }
            }
        }
    }

    // ---- stream remaining chunks (no barriers, no collectives in common path) ----
    for (int ch = 1; ch < nchunks; ch++) {
        const int base = ch * CHUNK_F4;
        float4 v[F4PT];
#pragma unroll
        for (int q = 0; q < F4PT; q++) {
            int f4i = base + q * NT + tid;
            v[q] = (f4i < nf4) ? rp[f4i] : make_float4(NEG, NEG, NEG, NEG);
        }
#pragma unroll
        for (int q = 0; q < F4PT; q++) {
            const float4 a = v[q];
            const float gm = fmaxf(fmaxf(a.x, a.y), fmaxf(a.z, a.w));
            if (gm >= tf) {
                const int f4i = base + q * NT + tid;
                const float vv[4] = {a.x, a.y, a.z, a.w};
#pragma unroll
                for (int e = 0; e < 4; e++) {
                    if (vv[e] >= tf) {
                        int s = atomicAdd(&sh.cnt, 1);
                        if (s < BUF_N)
                            buf[s] = ((u64)flip32(__float_as_uint(vv[e])) << 32)
                                   | (u32)(0xFFFFFFFFu - (u32)(f4i * 4 + e));
                    }
                }
            }
        }
    }
    // scalar tail (V % 4 != 0)
    for (int idx = nf4 * 4 + tid; idx < V; idx += NT) {
        float val = logits[(size_t)row * (size_t)V + idx];
        if (val >= tf) {
            int s = atomicAdd(&sh.cnt, 1);
            if (s < BUF_N)
                buf[s] = ((u64)flip32(__float_as_uint(val)) << 32)
                       | (u32)(0xFFFFFFFFu - (u32)idx);
        }
    }
    __syncthreads();

    // ---- phase 2: exact-k among candidates ----
    const int cnt = min(sh.cnt, BUF_N);
    for (int i = tid; i < NBINS; i += NT) hist[i] = 0u;
    __syncthreads();
    for (int i = tid; i < cnt; i += NT)
        atomicAdd(&hist[(u32)(buf[i] >> 32) >> BINSHIFT], 1u);
    __syncthreads();
    select_threshold(hist, k, &sh.thr2, partial);
    const u32 thr2 = sh.thr2;

    for (int i = tid; i < cnt; i += NT) {
        u64 key = buf[i];
        if ((u32)(key >> 32) >= thr2) {
            int p = atomicAdd(&sh.cnt2, 1);
            if (p < EPI_N) ep[p] = key;
        }
    }
    __syncthreads();
    const int c2 = min(sh.cnt2, EPI_N);

    // ---- bitonic sort finalists desc (value desc, index asc on ties) ----
    int n = 1;
    while (n < c2) n <<= 1;
    for (int j = c2 + tid; j < n; j += NT) ep[j] = 0ull;
    __syncthreads();
    for (int k2 = 2; k2 <= n; k2 <<= 1) {
        for (int s = k2 >> 1; s > 0; s >>= 1) {
            if (tid < n) {      // n <= 512 <= NT: one element pair region per thread
                int j = tid;
                int l = j ^ s;
                if (l > j) {
                    u64 a = ep[j], b = ep[l];
                    bool desc = ((j & k2) == 0);
                    if ((a < b) == desc) { ep[j] = b; ep[l] = a; }
                }
            }
            __syncthreads();
        }
    }

    // ---- unpack: IEEE division (fast-math-immune) ----
    const int L = min(c2, MAXEPI);
    for (int i = tid; i < L; i += NT) {
        u64 key = ep[i];
        sh.x[i]  = __fdiv_rn(__uint_as_float(unflip32((u32)(key >> 32))), 0.8f);
        sh.id[i] = (int)(0xFFFFFFFFu - (u32)(key & 0xFFFFFFFFu));
    }
    __syncthreads();

    // ---- serial epilogue — byte-identical to the passing R11/R13 kernel ----
    if (tid == 0) {
        int ans = V;
        if (L >= 1) {
            int kc = min(k, L);
            const float x0 = sh.x[0];
            const float kth = sh.x[kc - 1];
            int kk = kc;
            while (kk < L && sh.x[kk] >= kth) kk++;

            float d1 = 0.f;
            for (int i = 0; i < kk; i++) {
                float ee = expf(__fadd_rn(sh.x[i], -x0));
                sh.e[i] = ee;
                d1 = __fadd_rn(d1, ee);
            }
            float cprev = 0.f;
            int m = 0;
            for (int i = 0; i < kk; i++) {
                if (i > 0 && cprev > 0.9f) break;
                m++;
                cprev = __fadd_rn(cprev, __fdiv_rn(sh.e[i], d1));
            }
            for (int i = 1; i < m; i++) {
                int idv = sh.id[i]; float ev = sh.e[i]; int j = i - 1;
                while (j >= 0 && sh.id[j] > idv) {
                    sh.id[j + 1] = sh.id[j]; sh.e[j + 1] = sh.e[j]; j--;
                }
                sh.id[j + 1] = idv; sh.e[j + 1] = ev;
            }
            float d2 = 0.f;
            for (int i = 0; i < m; i++) d2 = __fadd_rn(d2, sh.e[i]);

            const float uu = u ? u[row] : 0.5f;
            float S = 0.f;
            for (int i = 0; i < m; i++) {
                S = __fadd_rn(S, __fdiv_rn(sh.e[i], d2));
                if (S > uu) { ans = sh.id[i]; break; }
            }
        }
        out[row] = (float)ans;   // float32 output (ids < 2^24 exact)
    }
}

extern "C" void kernel_launch(void* const* d_in, const int* in_sizes, int n_in,
                              void* d_out, int out_size) {
    int li = 0;
    for (int i = 1; i < n_in; i++)
        if (in_sizes[i] > in_sizes[li]) li = i;

    const int B = out_size;
    const float* logits = (const float*)d_in[li];
    const float* u = nullptr;
    const int* kp = nullptr;
    for (int i = 0; i < n_in; i++) {
        if (i == li) continue;
        if (in_sizes[i] == B) u = (const float*)d_in[i];
        else if (in_sizes[i] == 1) kp = (const int*)d_in[i];
    }
    if (!u) {
        for (int i = 0; i < n_in; i++)
            if (i != li && in_sizes[i] != 1) { u = (const float*)d_in[i]; break; }
    }

    int V = in_sizes[li] / B;
    if (V * B != in_sizes[li]) {
        int Vb = in_sizes[li] / 4 / B;
        if (Vb * B * 4 == in_sizes[li]) V = Vb;
    }

    Sampler_24446953849417_kernel<<<B, NT>>>(logits, u, kp, (float*)d_out, V);
}

// round 15
// speedup vs baseline: 3.0702x; 1.1678x over previous
#include <cuda_runtime.h>
#include <cstdint>
#include <math.h>

// Sampler: temperature 0.8, top-k, top-p 0.9, inverse-CDF multinomial. f32 output.
// Single kernel, one block per row. Histogram-free: moment-based threshold
// (t = mu + c*sigma from chunk 0) verified post-hoc by exact survivor count
// (cnt >= k  =>  top-k subset of {x >= t}, provably). Bounded retry if the
// count check fails (never on Gaussian logits). Candidates sorted in-place;
// epilogue byte-identical to the passing R11/R14 kernel.

#define NT 1024
#define F4PT 8
#define CHUNK_F4 (NT * F4PT)        // 8192 float4 = 32768 floats / chunk
#define BUF_N 4096                  // candidate buffer (u64 keys), pow2
#define MAXEPI 256                  // epilogue working set

typedef unsigned long long u64;
typedef unsigned int u32;

__device__ __forceinline__ u32 flip32(u32 f) {
    return (f & 0x80000000u) ? ~f : (f | 0x80000000u);
}
__device__ __forceinline__ u32 unflip32(u32 g) {
    return (g & 0x80000000u) ? (g & 0x7FFFFFFFu) : ~g;
}

struct Sh {
    int cnt;
    float red1[32];
    float red2[32];
    float mu, sg;
    float x[MAXEPI];
    float e[MAXEPI];
    int   id[MAXEPI];
};

__global__ __launch_bounds__(NT)
void Sampler_24446953849417_kernel(const float* __restrict__ logits,
                                   const float* __restrict__ u,
                                   const int* __restrict__ kptr,
                                   float* __restrict__ out, int V)
{
    __shared__ u64 buf[BUF_N];      // 32 KB
    __shared__ Sh sh;               // ~3.3 KB

    const int row = blockIdx.x;
    const int tid = threadIdx.x;
    const int lane = tid & 31;
    const int wid = tid >> 5;

    const float4* __restrict__ rp =
        reinterpret_cast<const float4*>(logits + (size_t)row * (size_t)V);
    const int nf4 = V >> 2;
    const int nchunks = (nf4 + CHUNK_F4 - 1) / CHUNK_F4;
    const float NEG = __int_as_float(0xff800000);

    int k = 50;
    if (kptr) {
        int kv = kptr[0];
        if (kv >= 1 && kv <= 100000) k = kv;
        else {
            float kf = __int_as_float(kv);
            if (kf >= 1.0f && kf <= 100000.0f) k = (int)kf;
        }
    }
    k = max(1, min(k, MAXEPI));

    // ---- stats over chunk 0 (shuffle-only block reduction, no atomics) ----
    {
        float s1 = 0.f, s2 = 0.f;
#pragma unroll
        for (int q = 0; q < F4PT; q++) {
            int f4i = q * NT + tid;
            if (f4i < nf4) {
                float4 a = rp[f4i];
                s1 += a.x + a.y + a.z + a.w;
                s2 += a.x * a.x + a.y * a.y + a.z * a.z + a.w * a.w;
            }
        }
#pragma unroll
        for (int d = 16; d > 0; d >>= 1) {
            s1 += __shfl_down_sync(0xffffffffu, s1, d);
            s2 += __shfl_down_sync(0xffffffffu, s2, d);
        }
        if (lane == 0) { sh.red1[wid] = s1; sh.red2[wid] = s2; }
        __syncthreads();
        if (wid == 0) {
            float t1 = sh.red1[lane];
            float t2 = sh.red2[lane];
#pragma unroll
            for (int d = 16; d > 0; d >>= 1) {
                t1 += __shfl_down_sync(0xffffffffu, t1, d);
                t2 += __shfl_down_sync(0xffffffffu, t2, d);
            }
            if (lane == 0) {
                float n0 = (float)min(CHUNK_F4 * 4, nf4 * 4);
                float mu = t1 / n0;
                float var = t2 / n0 - mu * mu;
                sh.mu = mu;
                sh.sg = sqrtf(fmaxf(var, 0.f));
            }
        }
        __syncthreads();
    }
    const float mu = sh.mu;
    const float sg = sh.sg;

    // ---- stream with post-hoc verified threshold (bounded retries) ----
    float c = 3.0f;
    float t = mu + c * sg;
    int cnt = 0;
    for (int att = 0; att < 8; att++) {
        if (tid == 0) sh.cnt = 0;
        __syncthreads();

        for (int ch = 0; ch < nchunks; ch++) {
            const int base = ch * CHUNK_F4;
            float4 v[F4PT];
#pragma unroll
            for (int q = 0; q < F4PT; q++) {
                int f4i = base + q * NT + tid;
                v[q] = (f4i < nf4) ? rp[f4i] : make_float4(NEG, NEG, NEG, NEG);
            }
#pragma unroll
            for (int q = 0; q < F4PT; q++) {
                const float4 a = v[q];
                const float gm = fmaxf(fmaxf(a.x, a.y), fmaxf(a.z, a.w));
                if (gm >= t) {
                    const int f4i = base + q * NT + tid;
                    const float vv[4] = {a.x, a.y, a.z, a.w};
#pragma unroll
                    for (int e = 0; e < 4; e++) {
                        if (vv[e] >= t) {   // OOB pads are -inf -> false
                            int s = atomicAdd(&sh.cnt, 1);
                            if (s < BUF_N)
                                buf[s] = ((u64)flip32(__float_as_uint(vv[e])) << 32)
                                       | (u32)(0xFFFFFFFFu - (u32)(f4i * 4 + e));
                        }
                    }
                }
            }
        }
        // scalar tail (V % 4 != 0)
        for (int idx = nf4 * 4 + tid; idx < V; idx += NT) {
            float val = logits[(size_t)row * (size_t)V + idx];
            if (val >= t) {
                int s = atomicAdd(&sh.cnt, 1);
                if (s < BUF_N)
                    buf[s] = ((u64)flip32(__float_as_uint(val)) << 32)
                           | (u32)(0xFFFFFFFFu - (u32)idx);
            }
        }
        __syncthreads();

        cnt = sh.cnt;
        // cnt >= k  =>  {x >= t} contains the full top-k (+ all its ties): proven.
        if ((cnt >= k && cnt <= BUF_N) || att == 7) break;
        c = (cnt < k) ? (c - 0.7f) : (c + 0.6f);
        t = mu + c * sg;
        __syncthreads();   // protect buf/cnt reset ordering on retry
    }
    cnt = min(cnt, BUF_N);

    // ---- bitonic sort candidates desc (value desc, index asc on ties) ----
    int n = 1;
    while (n < cnt) n <<= 1;
    for (int j = cnt + tid; j < n; j += NT) buf[j] = 0ull;   // pad sorts last
    __syncthreads();
    for (int k2 = 2; k2 <= n; k2 <<= 1) {
        for (int s = k2 >> 1; s > 0; s >>= 1) {
            for (int j = tid; j < n; j += NT) {
                int l = j ^ s;
                if (l > j) {
                    u64 a = buf[j], b = buf[l];
                    bool desc = ((j & k2) == 0);
                    if ((a < b) == desc) { buf[j] = b; buf[l] = a; }
                }
            }
            __syncthreads();
        }
    }

    // ---- unpack top candidates: IEEE division (fast-math-immune) ----
    const int L = min(cnt, MAXEPI);
    for (int i = tid; i < L; i += NT) {
        u64 key = buf[i];
        sh.x[i]  = __fdiv_rn(__uint_as_float(unflip32((u32)(key >> 32))), 0.8f);
        sh.id[i] = (int)(0xFFFFFFFFu - (u32)(key & 0xFFFFFFFFu));
    }
    __syncthreads();

    // ---- serial epilogue — byte-identical to the passing R11/R14 kernel ----
    if (tid == 0) {
        int ans = V;
        if (L >= 1) {
            int kc = min(k, L);
            const float x0 = sh.x[0];
            const float kth = sh.x[kc - 1];
            int kk = kc;
            while (kk < L && sh.x[kk] >= kth) kk++;

            float d1 = 0.f;
            for (int i = 0; i < kk; i++) {
                float ee = expf(__fadd_rn(sh.x[i], -x0));
                sh.e[i] = ee;
                d1 = __fadd_rn(d1, ee);
            }
            float cprev = 0.f;
            int m = 0;
            for (int i = 0; i < kk; i++) {
                if (i > 0 && cprev > 0.9f) break;
                m++;
                cprev = __fadd_rn(cprev, __fdiv_rn(sh.e[i], d1));
            }
            for (int i = 1; i < m; i++) {
                int idv = sh.id[i]; float ev = sh.e[i]; int j = i - 1;
                while (j >= 0 && sh.id[j] > idv) {
                    sh.id[j + 1] = sh.id[j]; sh.e[j + 1] = sh.e[j]; j--;
                }
                sh.id[j + 1] = idv; sh.e[j + 1] = ev;
            }
            float d2 = 0.f;
            for (int i = 0; i < m; i++) d2 = __fadd_rn(d2, sh.e[i]);

            const float uu = u ? u[row] : 0.5f;
            float S = 0.f;
            for (int i = 0; i < m; i++) {
                S = __fadd_rn(S, __fdiv_rn(sh.e[i], d2));
                if (S > uu) { ans = sh.id[i]; break; }
            }
        }
        out[row] = (float)ans;   // float32 output (ids < 2^24 exact)
    }
}

extern "C" void kernel_launch(void* const* d_in, const int* in_sizes, int n_in,
                              void* d_out, int out_size) {
    int li = 0;
    for (int i = 1; i < n_in; i++)
        if (in_sizes[i] > in_sizes[li]) li = i;

    const int B = out_size;
    const float* logits = (const float*)d_in[li];
    const float* u = nullptr;
    const int* kp = nullptr;
    for (int i = 0; i < n_in; i++) {
        if (i == li) continue;
        if (in_sizes[i] == B) u = (const float*)d_in[i];
        else if (in_sizes[i] == 1) kp = (const int*)d_in[i];
    }
    if (!u) {
        for (int i = 0; i < n_in; i++)
            if (i != li && in_sizes[i] != 1) { u = (const float*)d_in[i]; break; }
    }

    int V = in_sizes[li] / B;
    if (V * B != in_sizes[li]) {
        int Vb = in_sizes[li] / 4 / B;
        if (Vb * B * 4 == in_sizes[li]) V = Vb;
    }

    Sampler_24446953849417_kernel<<<B, NT>>>(logits, u, kp, (float*)d_out, V);
}

// round 16
// speedup vs baseline: 5.4665x; 1.7805x over previous
#include <cuda_runtime.h>
#include <cstdint>
#include <math.h>

// Sampler: temperature 0.8, top-k, top-p 0.9, inverse-CDF multinomial. f32 output.
// Single kernel, one block per row. Moment-based threshold (post-hoc verified).
// This round: epilogue restructured — elementwise ops parallel across 64 threads,
// sequential fp chains kept bit-exact but register-resident, survivor sort bitonic.

#define NT 1024
#define F4PT 8
#define CHUNK_F4 (NT * F4PT)        // 32768 floats / chunk
#define BUF_N 4096                  // candidate buffer (u64 keys), pow2
#define MAXEPI 256
#define FEPI 64                     // fast-path epilogue width

typedef unsigned long long u64;
typedef unsigned int u32;

__device__ __forceinline__ u32 flip32(u32 f) {
    return (f & 0x80000000u) ? ~f : (f | 0x80000000u);
}
__device__ __forceinline__ u32 unflip32(u32 g) {
    return (g & 0x80000000u) ? (g & 0x7FFFFFFFu) : ~g;
}

struct Sh {
    int cnt;
    float red1[32];
    float red2[32];
    float mu, sg;
    int   kk, m;
    float x0, d1, d2;
    float x[MAXEPI];
    float e[MAXEPI];
    int   id[MAXEPI];
    float p[FEPI];
};

__global__ __launch_bounds__(NT)
void Sampler_24446953849417_kernel(const float* __restrict__ logits,
                                   const float* __restrict__ u,
                                   const int* __restrict__ kptr,
                                   float* __restrict__ out, int V)
{
    __shared__ u64 buf[BUF_N];      // 32 KB
    __shared__ Sh sh;               // ~3.6 KB

    const int row = blockIdx.x;
    const int tid = threadIdx.x;
    const int lane = tid & 31;
    const int wid = tid >> 5;

    const float4* __restrict__ rp =
        reinterpret_cast<const float4*>(logits + (size_t)row * (size_t)V);
    const int nf4 = V >> 2;
    const int nchunks = (nf4 + CHUNK_F4 - 1) / CHUNK_F4;
    const float NEG = __int_as_float(0xff800000);

    int k = 50;
    if (kptr) {
        int kv = kptr[0];
        if (kv >= 1 && kv <= 100000) k = kv;
        else {
            float kf = __int_as_float(kv);
            if (kf >= 1.0f && kf <= 100000.0f) k = (int)kf;
        }
    }
    k = max(1, min(k, MAXEPI));

    // ---- stats over an 8192-elem sample (shuffle-only reduction, no atomics) ----
    {
        float s1 = 0.f, s2 = 0.f;
#pragma unroll
        for (int q = 0; q < 2; q++) {
            int f4i = q * NT + tid;
            if (f4i < nf4) {
                float4 a = rp[f4i];
                s1 += a.x + a.y + a.z + a.w;
                s2 += a.x * a.x + a.y * a.y + a.z * a.z + a.w * a.w;
            }
        }
#pragma unroll
        for (int d = 16; d > 0; d >>= 1) {
            s1 += __shfl_down_sync(0xffffffffu, s1, d);
            s2 += __shfl_down_sync(0xffffffffu, s2, d);
        }
        if (lane == 0) { sh.red1[wid] = s1; sh.red2[wid] = s2; }
        __syncthreads();
        if (wid == 0) {
            float t1 = sh.red1[lane];
            float t2 = sh.red2[lane];
#pragma unroll
            for (int d = 16; d > 0; d >>= 1) {
                t1 += __shfl_down_sync(0xffffffffu, t1, d);
                t2 += __shfl_down_sync(0xffffffffu, t2, d);
            }
            if (lane == 0) {
                float n0 = (float)min(2 * NT * 4, nf4 * 4);
                float mu = t1 / n0;
                float var = t2 / n0 - mu * mu;
                sh.mu = mu;
                sh.sg = sqrtf(fmaxf(var, 0.f));
            }
        }
        __syncthreads();
    }
    const float mu = sh.mu;
    const float sg = sh.sg;

    // ---- stream with post-hoc verified threshold (bounded retries) ----
    float c = 3.0f;
    float t = mu + c * sg;
    int cnt = 0;
    for (int att = 0; att < 8; att++) {
        if (tid == 0) sh.cnt = 0;
        __syncthreads();

        for (int ch = 0; ch < nchunks; ch++) {
            const int base = ch * CHUNK_F4;
            float4 v[F4PT];
#pragma unroll
            for (int q = 0; q < F4PT; q++) {
                int f4i = base + q * NT + tid;
                v[q] = (f4i < nf4) ? rp[f4i] : make_float4(NEG, NEG, NEG, NEG);
            }
#pragma unroll
            for (int q = 0; q < F4PT; q++) {
                const float4 a = v[q];
                const float gm = fmaxf(fmaxf(a.x, a.y), fmaxf(a.z, a.w));
                if (gm >= t) {
                    const int f4i = base + q * NT + tid;
                    const float vv[4] = {a.x, a.y, a.z, a.w};
#pragma unroll
                    for (int e = 0; e < 4; e++) {
                        if (vv[e] >= t) {   // OOB pads are -inf -> false
                            int s = atomicAdd(&sh.cnt, 1);
                            if (s < BUF_N)
                                buf[s] = ((u64)flip32(__float_as_uint(vv[e])) << 32)
                                       | (u32)(0xFFFFFFFFu - (u32)(f4i * 4 + e));
                        }
                    }
                }
            }
        }
        for (int idx = nf4 * 4 + tid; idx < V; idx += NT) {   // scalar tail
            float val = logits[(size_t)row * (size_t)V + idx];
            if (val >= t) {
                int s = atomicAdd(&sh.cnt, 1);
                if (s < BUF_N)
                    buf[s] = ((u64)flip32(__float_as_uint(val)) << 32)
                           | (u32)(0xFFFFFFFFu - (u32)idx);
            }
        }
        __syncthreads();

        cnt = sh.cnt;
        // cnt >= k  =>  {x >= t} provably contains the full top-k (+ ties).
        if ((cnt >= k && cnt <= BUF_N) || att == 7) break;
        c = (cnt < k) ? (c - 0.7f) : (c + 0.6f);
        t = mu + c * sg;
        __syncthreads();
    }
    cnt = min(cnt, BUF_N);

    // ---- bitonic sort candidates desc (value desc, index asc on ties) ----
    int n = 1;
    while (n < cnt) n <<= 1;
    for (int j = cnt + tid; j < n; j += NT) buf[j] = 0ull;
    __syncthreads();
    for (int k2 = 2; k2 <= n; k2 <<= 1) {
        for (int s = k2 >> 1; s > 0; s >>= 1) {
            for (int j = tid; j < n; j += NT) {
                int l = j ^ s;
                if (l > j) {
                    u64 a = buf[j], b = buf[l];
                    bool desc = ((j & k2) == 0);
                    if ((a < b) == desc) { buf[j] = b; buf[l] = a; }
                }
            }
            __syncthreads();
        }
    }

    // ---- unpack (value desc, stable ties == argsort(-x)) ----
    const int L = min(cnt, MAXEPI);
    for (int i = tid; i < L; i += NT) {
        u64 key = buf[i];
        sh.x[i]  = __fdiv_rn(__uint_as_float(unflip32((u32)(key >> 32))), 0.8f);
        sh.id[i] = (int)(0xFFFFFFFFu - (u32)(key & 0xFFFFFFFFu));
    }
    __syncthreads();

    // ---- header: kc, x0, kth, kk (cheap serial) ----
    if (tid == 0) {
        if (L < 1) { sh.kk = 0; }
        else {
            int kc = min(k, L);
            sh.x0 = sh.x[0];
            float kth = sh.x[kc - 1];
            int kk = kc;
            while (kk < L && sh.x[kk] >= kth) kk++;   // keep ties, as reference
            sh.kk = kk;
        }
    }
    __syncthreads();
    const int kk = sh.kk;
    const float uu = u ? u[row] : 0.5f;

    if (kk >= 1 && kk <= FEPI) {
        // ================= FAST epilogue (bit-exact restructuring) =================
        const float x0 = sh.x0;
        if (tid < FEPI)
            sh.e[tid] = (tid < kk) ? expf(__fadd_rn(sh.x[tid], -x0)) : 0.f;
        __syncthreads();
        if (tid == 0) {
            float d1 = 0.f;
#pragma unroll
            for (int i = 0; i < FEPI; i++) d1 = __fadd_rn(d1, sh.e[i]); // +0 pads exact
            sh.d1 = d1;
        }
        __syncthreads();
        if (tid < FEPI)
            sh.p[tid] = (tid < kk) ? __fdiv_rn(sh.e[tid], sh.d1) : 0.f;
        __syncthreads();
        if (tid == 0) {
            // nucleus: m = #iterations before cdf[i-1] > 0.9 (monotone -> prefix)
            float cp = 0.f; int m = 0;
#pragma unroll
            for (int i = 0; i < FEPI; i++) {
                bool act = (i < kk) && (i == 0 || !(cp > 0.9f));
                if (act) { m++; cp = __fadd_rn(cp, sh.p[i]); }
            }
            sh.m = m;
        }
        __syncthreads();
        const int m = sh.m;

        // sort survivors by vocab id ascending (exact integer sort, 64-wide bitonic)
        if (tid < FEPI) {
            buf[tid] = (tid < m)
                ? (((u64)(u32)sh.id[tid] << 32) | (u64)__float_as_uint(sh.e[tid]))
                : ((u64)0xFFFFFFFFu << 32);   // pad: id=max, e=+0.0f
        }
        __syncthreads();
        for (int k2 = 2; k2 <= FEPI; k2 <<= 1) {
            for (int s = k2 >> 1; s > 0; s >>= 1) {
                if (tid < FEPI) {
                    int j = tid, l = j ^ s;
                    if (l > j) {
                        u64 a = buf[j], b = buf[l];
                        bool asc = ((j & k2) == 0);
                        if ((a > b) == asc) { buf[j] = b; buf[l] = a; }
                    }
                }
                __syncthreads();
            }
        }
        if (tid < FEPI) sh.e[tid] = __uint_as_float((u32)(buf[tid] & 0xFFFFFFFFu));
        __syncthreads();
        if (tid == 0) {
            float d2 = 0.f;
#pragma unroll
            for (int i = 0; i < FEPI; i++) d2 = __fadd_rn(d2, sh.e[i]); // pads +0 exact
            sh.d2 = d2;
        }
        __syncthreads();
        if (tid < FEPI)
            sh.p[tid] = (tid < m) ? __fdiv_rn(sh.e[tid], sh.d2) : 0.f;
        __syncthreads();
        if (tid == 0) {
            // idx = #{i<m : S_i <= u}; S monotone -> ans = id[idx] (V if idx==m)
            float S = 0.f; int idx = 0;
#pragma unroll
            for (int i = 0; i < FEPI; i++) {
                if (i < m) {
                    S = __fadd_rn(S, sh.p[i]);
                    if (S <= uu) idx++;
                }
            }
            int ans = (idx < m) ? (int)(buf[idx] >> 32) : V;
            out[row] = (float)ans;
        }
    } else {
        // ============ fallback: verbatim R15 serial epilogue (kk==0 or kk>64) ============
        if (tid == 0) {
            int ans = V;
            if (L >= 1) {
                int kc = min(k, L);
                const float x0 = sh.x[0];
                const float kth = sh.x[kc - 1];
                int kk2 = kc;
                while (kk2 < L && sh.x[kk2] >= kth) kk2++;

                float d1 = 0.f;
                for (int i = 0; i < kk2; i++) {
                    float ee = expf(__fadd_rn(sh.x[i], -x0));
                    sh.e[i] = ee;
                    d1 = __fadd_rn(d1, ee);
                }
                float cprev = 0.f;
                int m = 0;
                for (int i = 0; i < kk2; i++) {
                    if (i > 0 && cprev > 0.9f) break;
                    m++;
                    cprev = __fadd_rn(cprev, __fdiv_rn(sh.e[i], d1));
                }
                for (int i = 1; i < m; i++) {
                    int idv = sh.id[i]; float ev = sh.e[i]; int j = i - 1;
                    while (j >= 0 && sh.id[j] > idv) {
                        sh.id[j + 1] = sh.id[j]; sh.e[j + 1] = sh.e[j]; j--;
                    }
                    sh.id[j + 1] = idv; sh.e[j + 1] = ev;
                }
                float d2 = 0.f;
                for (int i = 0; i < m; i++) d2 = __fadd_rn(d2, sh.e[i]);

                float S = 0.f;
                for (int i = 0; i < m; i++) {
                    S = __fadd_rn(S, __fdiv_rn(sh.e[i], d2));
                    if (S > uu) { ans = sh.id[i]; break; }
                }
            }
            out[row] = (float)ans;
        }
    }
}

extern "C" void kernel_launch(void* const* d_in, const int* in_sizes, int n_in,
                              void* d_out, int out_size) {
    int li = 0;
    for (int i = 1; i < n_in; i++)
        if (in_sizes[i] > in_sizes[li]) li = i;

    const int B = out_size;
    const float* logits = (const float*)d_in[li];
    const float* u = nullptr;
    const int* kp = nullptr;
    for (int i = 0; i < n_in; i++) {
        if (i == li) continue;
        if (in_sizes[i] == B) u = (const float*)d_in[i];
        else if (in_sizes[i] == 1) kp = (const int*)d_in[i];
    }
    if (!u) {
        for (int i = 0; i < n_in; i++)
            if (i != li && in_sizes[i] != 1) { u = (const float*)d_in[i]; break; }
    }

    int V = in_sizes[li] / B;
    if (V * B != in_sizes[li]) {
        int Vb = in_sizes[li] / 4 / B;
        if (Vb * B * 4 == in_sizes[li]) V = Vb;
    }

    Sampler_24446953849417_kernel<<<B, NT>>>(logits, u, kp, (float*)d_out, V);
}